// round 13
// baseline (speedup 1.0000x reference)
#include <cuda_runtime.h>
#include <cuda_fp16.h>
#include <cstdint>

#define N_NODES 50000
#define N_EDGES 800000
#define CH 128
#define OUTC 64
#define NG 256
#define CAP 128                 // bucket capacity per node

#define AGG_WARPS 16

// GEMM tiling: 128 rows x 128 cols per block, 8 warps, mma.m16n8k16
#define GM 128
#define GT 256
#define LDA 136                  // halves, 272B rows -> conflict-free ldmatrix
#define LDB 136
#define GEMM_SMEM ((GM * LDA + CH * LDB) * 2)

// ---------------- scratch (device globals; no allocation allowed) ----------
// INVARIANT: g_cursor/g_cursor2/g_pooled are all-zero before each
// kernel_launch (zero-init at load; k_out restores zero afterwards).
__device__ int g_csr_src[N_NODES * CAP];
__device__ int g_cursor[N_NODES];      // front-shard in-degree; reset by k_out
__device__ int g_cursor2[N_NODES];     // back-shard in-degree; reset by k_out
__device__ int g_batch[N_NODES];
__device__ __half g_h[(size_t)N_NODES * CH];   // h, then h' = dinv*h after k_scale
__device__ __half g_w1h[CH * CH];
__device__ unsigned g_pooled[NG * CH]; // reset to 0 by k_out

// ---------------- mma helpers ----------------------------------------------
__device__ __forceinline__ void ldsm_x4(uint32_t* r, uint32_t addr) {
    asm volatile("ldmatrix.sync.aligned.m8n8.x4.shared.b16 {%0,%1,%2,%3}, [%4];"
        : "=r"(r[0]), "=r"(r[1]), "=r"(r[2]), "=r"(r[3]) : "r"(addr));
}
__device__ __forceinline__ void ldsm_x4_t(uint32_t* r, uint32_t addr) {
    asm volatile("ldmatrix.sync.aligned.m8n8.x4.trans.shared.b16 {%0,%1,%2,%3}, [%4];"
        : "=r"(r[0]), "=r"(r[1]), "=r"(r[2]), "=r"(r[3]) : "r"(addr));
}
__device__ __forceinline__ void mma16816(float* d, const uint32_t* a, const uint32_t* b) {
    asm volatile("mma.sync.aligned.m16n8k16.row.col.f32.f16.f16.f32 "
        "{%0,%1,%2,%3}, {%4,%5,%6,%7}, {%8,%9}, {%0,%1,%2,%3};"
        : "+f"(d[0]), "+f"(d[1]), "+f"(d[2]), "+f"(d[3])
        : "r"(a[0]), "r"(a[1]), "r"(a[2]), "r"(a[3]), "r"(b[0]), "r"(b[1]));
}

// ---------------- prep: self-detecting dtype + sharded bucket scatter ------
// Edge 0 of each thread fills its bucket from the FRONT (g_cursor), edge 1
// from the BACK (g_cursor2): halves per-address L2-atomic contention.
__global__ void k_prep(const unsigned* __restrict__ ei,
                       const unsigned* __restrict__ bt) {
    __shared__ int s64e, s64b;
    {
        int w = threadIdx.x >> 5, lane = threadIdx.x & 31;
        if (w == 0) {
            unsigned v = ei[2 * lane * 999 + 1];     // odd 32-bit words
            unsigned m = __ballot_sync(0xffffffffu, v == 0u);
            if (lane == 0) s64e = (m == 0xffffffffu);
        } else if (w == 1) {
            unsigned v = bt[2001 + 2 * lane * 747];  // sorted batch, idx>2000
            unsigned m = __ballot_sync(0xffffffffu, v == 0u);
            if (lane == 0) s64b = (m == 0xffffffffu);
        }
    }
    __syncthreads();
    int t = blockIdx.x * blockDim.x + threadIdx.x;
    if (t < N_NODES / 2) {
        int b0, b1;
        if (s64b) {
            uint4 v = ((const uint4*)bt)[t];
            b0 = (int)v.x; b1 = (int)v.z;
        } else {
            uint2 v = ((const uint2*)bt)[t];
            b0 = (int)v.x; b1 = (int)v.y;
        }
        *(int2*)&g_batch[2 * t] = make_int2(b0, b1);
    }
    if (t >= N_EDGES / 2) return;
    int s0, s1, d0, d1;
    if (s64e) {
        uint4 a = ((const uint4*)ei)[t];
        uint4 b = ((const uint4*)ei)[N_EDGES / 2 + t];
        s0 = (int)a.x; s1 = (int)a.z;
        d0 = (int)b.x; d1 = (int)b.z;
    } else {
        uint2 a = ((const uint2*)ei)[t];
        uint2 b = ((const uint2*)ei)[N_EDGES / 2 + t];
        s0 = (int)a.x; s1 = (int)a.y;
        d0 = (int)b.x; d1 = (int)b.y;
    }
    int p0 = atomicAdd(&g_cursor[d0], 1);
    g_csr_src[d0 * CAP + min(p0, CAP - 1)] = s0;                 // front
    int p1 = atomicAdd(&g_cursor2[d1], 1);
    g_csr_src[d1 * CAP + CAP - 1 - min(p1, CAP - 1)] = s1;       // back
}

// ---------------- W1 -> fp16 ----------------------------------------------
__global__ void k_wconv(const float* __restrict__ W1) {
    int t = blockIdx.x * blockDim.x + threadIdx.x;   // 4096 threads, 4 elems each
    float4 v = ((const float4*)W1)[t];
    __half2 h01 = __floats2half2_rn(v.x, v.y);
    __half2 h23 = __floats2half2_rn(v.z, v.w);
    ((uint2*)g_w1h)[t] = make_uint2(*(unsigned*)&h01, *(unsigned*)&h23);
}

// ---------------- h = x @ W1 via HMMA (128-row tiles: half the W1 reloads) --
__global__ void __launch_bounds__(GT) k_gemm(const float* __restrict__ x) {
    extern __shared__ __half sm[];
    __half* As = sm;                 // [GM][LDA]
    __half* Bs = sm + GM * LDA;      // [CH][LDB]
    int tid = threadIdx.x;
    int row0 = blockIdx.x * GM;

#pragma unroll
    for (int i = 0; i < 16; i++) {
        int idx4 = tid + i * GT;                     // float4 index in 128x32
        int r = idx4 >> 5, c4 = idx4 & 31;
        int gr = row0 + r;
        float4 v = (gr < N_NODES) ? ((const float4*)x)[(size_t)gr * 32 + c4]
                                  : make_float4(0.f, 0.f, 0.f, 0.f);
        __half2 h01 = __floats2half2_rn(v.x, v.y);
        __half2 h23 = __floats2half2_rn(v.z, v.w);
        *(uint2*)&As[r * LDA + c4 * 4] = make_uint2(*(unsigned*)&h01, *(unsigned*)&h23);
    }
#pragma unroll
    for (int i = 0; i < 8; i++) {
        int idx8 = tid + i * GT;                     // uint4 index in 128x16
        int r = idx8 >> 4, c8 = idx8 & 15;
        *(uint4*)&Bs[r * LDB + c8 * 8] = ((const uint4*)g_w1h)[(size_t)r * 16 + c8];
    }
    __syncthreads();

    int w = tid >> 5, lane = tid & 31;
    int m0 = w * 16;
    uint32_t a_base = (uint32_t)__cvta_generic_to_shared(As)
                    + ((m0 + (lane & 15)) * LDA + (lane >> 4) * 8) * 2;
    uint32_t b_base = (uint32_t)__cvta_generic_to_shared(Bs)
                    + ((lane & 15) * LDB + (lane >> 4) * 8) * 2;

    float acc[16][4];
#pragma unroll
    for (int j = 0; j < 16; j++)
#pragma unroll
        for (int q = 0; q < 4; q++) acc[j][q] = 0.f;

#pragma unroll
    for (int kk = 0; kk < 8; kk++) {
        uint32_t a[4];
        ldsm_x4(a, a_base + kk * 16 * 2);
#pragma unroll
        for (int jt = 0; jt < 8; jt++) {
            uint32_t b[4];
            ldsm_x4_t(b, b_base + (kk * 16 * LDB + jt * 16) * 2);
            mma16816(acc[2 * jt], a, b);
            mma16816(acc[2 * jt + 1], a, b + 2);
        }
    }

    int r_lo = row0 + m0 + (lane >> 2);
    int r_hi = r_lo + 8;
    int cbase = (lane & 3) * 2;
#pragma unroll
    for (int j = 0; j < 16; j++) {
        int col = j * 8 + cbase;
        if (r_lo < N_NODES) {
            __half2 v = __floats2half2_rn(acc[j][0], acc[j][1]);
            *(unsigned*)&g_h[(size_t)r_lo * CH + col] = *(unsigned*)&v;
        }
        if (r_hi < N_NODES) {
            __half2 v = __floats2half2_rn(acc[j][2], acc[j][3]);
            *(unsigned*)&g_h[(size_t)r_hi * CH + col] = *(unsigned*)&v;
        }
    }
}

// ---------------- scale: h' = dinv * h, warp per node ----------------------
__global__ void __launch_bounds__(256) k_scale() {
    int w = threadIdx.x >> 5, lane = threadIdx.x & 31;
    int node = blockIdx.x * 8 + w;                   // 6250 blocks * 8 warps
    if (node >= N_NODES) return;
    int cnt = g_cursor[node] + g_cursor2[node];
    float di = rsqrtf((float)(cnt + 1));
    uint2* row = (uint2*)&g_h[(size_t)node * CH];
    uint2 v = row[lane];
    float2 f01 = __half22float2(*(__half2*)&v.x);
    float2 f23 = __half22float2(*(__half2*)&v.y);
    __half2 o01 = __floats2half2_rn(f01.x * di, f01.y * di);
    __half2 o23 = __floats2half2_rn(f23.x * di, f23.y * di);
    row[lane] = make_uint2(*(unsigned*)&o01, *(unsigned*)&o23);
}

// ---------------- aggregation + bias + relu + pooled max (fused) -----------
// Two bucket segments (front c0, back c2); inner loops pure gather+add.
__global__ void __launch_bounds__(AGG_WARPS * 32) k_aggregate(
        const float* __restrict__ b1) {
    __shared__ float sval[AGG_WARPS * CH];
    __shared__ int sgid[AGG_WARPS];
    int tid = threadIdx.x;
    int w = tid >> 5, lane = tid & 31;
    int d = blockIdx.x * AGG_WARPS + w;              // < N_NODES (50000 % 16 == 0)

    int c0 = g_cursor[d], c2 = g_cursor2[d];
    float di = rsqrtf((float)(c0 + c2 + 1));
    const uint2* __restrict__ h2 = (const uint2*)g_h;

    uint2 hs = h2[(size_t)d * 32 + lane];            // self loop (pre-scaled)
    float2 s01 = __half22float2(*(__half2*)&hs.x);
    float2 s23 = __half22float2(*(__half2*)&hs.y);
    float ax = s01.x, ay = s01.y, az = s23.x, aw = s23.y;

    int e0 = d * CAP;
    // segment 1: [e0, e0 + min(c0,CAP));  segment 2: [e0+CAP-min(c2,CAP), e0+CAP)
#pragma unroll 1
    for (int seg = 0; seg < 2; seg++) {
        int e, e1;
        if (seg == 0) { e = e0; e1 = e0 + min(c0, CAP); }
        else          { e = e0 + CAP - min(c2, CAP); e1 = e0 + CAP; }
        for (; e + 3 < e1; e += 4) {
            int sA = g_csr_src[e],     sB = g_csr_src[e + 1];
            int sC = g_csr_src[e + 2], sD = g_csr_src[e + 3];
            uint2 hA = h2[(size_t)sA * 32 + lane];
            uint2 hB = h2[(size_t)sB * 32 + lane];
            uint2 hC = h2[(size_t)sC * 32 + lane];
            uint2 hD = h2[(size_t)sD * 32 + lane];
            float2 a01 = __half22float2(*(__half2*)&hA.x);
            float2 a23 = __half22float2(*(__half2*)&hA.y);
            float2 b01 = __half22float2(*(__half2*)&hB.x);
            float2 b23 = __half22float2(*(__half2*)&hB.y);
            float2 c01 = __half22float2(*(__half2*)&hC.x);
            float2 c23 = __half22float2(*(__half2*)&hC.y);
            float2 d01 = __half22float2(*(__half2*)&hD.x);
            float2 d23 = __half22float2(*(__half2*)&hD.y);
            ax += a01.x + b01.x + c01.x + d01.x;
            ay += a01.y + b01.y + c01.y + d01.y;
            az += a23.x + b23.x + c23.x + d23.x;
            aw += a23.y + b23.y + c23.y + d23.y;
        }
        for (; e < e1; e++) {
            int sA = g_csr_src[e];
            uint2 hA = h2[(size_t)sA * 32 + lane];
            float2 a01 = __half22float2(*(__half2*)&hA.x);
            float2 a23 = __half22float2(*(__half2*)&hA.y);
            ax += a01.x; ay += a01.y; az += a23.x; aw += a23.y;
        }
    }

    float4 bb = *(const float4*)&b1[lane * 4];
    float4 v;
    v.x = fmaxf(fmaf(ax, di, bb.x), 0.f);
    v.y = fmaxf(fmaf(ay, di, bb.y), 0.f);
    v.z = fmaxf(fmaf(az, di, bb.z), 0.f);
    v.w = fmaxf(fmaf(aw, di, bb.w), 0.f);
    *(float4*)&sval[w * CH + lane * 4] = v;
    if (lane == 0) sgid[w] = g_batch[d];
    __syncthreads();

    if (tid < CH) {
        int c = tid;
        int curg = sgid[0];
        float m = sval[c];
        for (int ww = 1; ww < AGG_WARPS; ww++) {
            int g = sgid[ww];
            float u = sval[ww * CH + c];
            if (g == curg) {
                m = fmaxf(m, u);
            } else {
                atomicMax(&g_pooled[curg * CH + c], __float_as_uint(m));
                curg = g; m = u;
            }
        }
        atomicMax(&g_pooled[curg * CH + c], __float_as_uint(m));
    }
}

// ---------------- out = relu(pooled @ W2 + b2); restore invariants ---------
__global__ void k_out(const float* __restrict__ W2, const float* __restrict__ b2,
                      float* __restrict__ out) {
    __shared__ float p[CH];
    int g = blockIdx.x, c = threadIdx.x;
    p[c]      = __uint_as_float(g_pooled[g * CH + c]);
    p[c + 64] = __uint_as_float(g_pooled[g * CH + c + 64]);
    __syncthreads();
    // restore zero-invariants for the next replay
    g_pooled[g * CH + c] = 0u;
    g_pooled[g * CH + c + 64] = 0u;
    {   // block g zeroes cursor slices [g*196, g*196+196) ∩ [0, N_NODES)
        int base = g * 196;
        for (int i = c; i < 196; i += OUTC) {
            int idx = base + i;
            if (idx < N_NODES) { g_cursor[idx] = 0; g_cursor2[idx] = 0; }
        }
    }
    float acc = b2[c];
#pragma unroll 8
    for (int k = 0; k < CH; k++)
        acc = fmaf(p[k], W2[k * OUTC + c], acc);
    out[g * OUTC + c] = fmaxf(acc, 0.f);
}

// ---------------- launch ---------------------------------------------------
extern "C" void kernel_launch(void* const* d_in, const int* in_sizes, int n_in,
                              void* d_out, int out_size) {
    const float *x = nullptr, *W1 = nullptr, *b1 = nullptr, *W2 = nullptr, *b2 = nullptr;
    const unsigned *ei = nullptr, *bt = nullptr;
    for (int i = 0; i < n_in; i++) {
        switch (in_sizes[i]) {
            case N_NODES * CH:    x  = (const float*)d_in[i]; break;
            case 2 * N_EDGES:     ei = (const unsigned*)d_in[i]; break;
            case N_NODES:         bt = (const unsigned*)d_in[i]; break;
            case CH * CH:         W1 = (const float*)d_in[i]; break;
            case CH:              b1 = (const float*)d_in[i]; break;
            case CH * OUTC:       W2 = (const float*)d_in[i]; break;
            case OUTC:            b2 = (const float*)d_in[i]; break;
        }
    }
    float* out = (float*)d_out;

    static cudaStream_t sB = nullptr;
    static cudaEvent_t evFork = nullptr, evJoin = nullptr;
    if (!sB) {
        cudaStreamCreateWithFlags(&sB, cudaStreamNonBlocking);
        cudaEventCreateWithFlags(&evFork, cudaEventDisableTiming);
        cudaEventCreateWithFlags(&evJoin, cudaEventDisableTiming);
        cudaFuncSetAttribute(k_gemm, cudaFuncAttributeMaxDynamicSharedMemorySize,
                             GEMM_SMEM);
    }

    // Fork: W-convert + tensor-core GEMM overlap the edge preprocessing.
    cudaEventRecord(evFork, 0);
    cudaStreamWaitEvent(sB, evFork, 0);
    k_wconv<<<16, 256, 0, sB>>>(W1);
    k_gemm<<<(N_NODES + GM - 1) / GM, GT, GEMM_SMEM, sB>>>(x);
    cudaEventRecord(evJoin, sB);

    // Main: prep, join gemm, scale h in place, aggregate, out.
    k_prep<<<(N_EDGES / 2 + 255) / 256, 256>>>(ei, bt);
    cudaStreamWaitEvent(0, evJoin, 0);               // h must exist for k_scale
    k_scale<<<N_NODES / 8, 256>>>();
    k_aggregate<<<N_NODES / AGG_WARPS, AGG_WARPS * 32>>>(b1);
    k_out<<<NG, OUTC>>>(W2, b2, out);
}

// round 14
// speedup vs baseline: 1.0787x; 1.0787x over previous
#include <cuda_runtime.h>
#include <cuda_fp16.h>
#include <cstdint>

#define N_NODES 50000
#define N_EDGES 800000
#define CH 128
#define OUTC 64
#define NG 256
#define CAP 128                 // bucket capacity per node

#define AGG_WARPS 16

// GEMM tiling: 64 rows x 128 cols per block, 4 warps, mma.m16n8k16
#define GM 64
#define LDA 136                  // halves, 272B rows -> conflict-free ldmatrix
#define LDB 136
#define GEMM_SMEM ((GM * LDA + CH * LDB) * 2)

// ---------------- scratch (device globals; no allocation allowed) ----------
// INVARIANT: g_cursor and g_pooled are all-zero before each kernel_launch
// (zero-init at load; k_out restores zero afterwards).
__device__ int g_csr_src[N_NODES * CAP];
__device__ int g_cursor[N_NODES];      // in-degree per node; reset by k_out
__device__ int g_batch[N_NODES];
__device__ __half g_h[(size_t)N_NODES * CH];   // h, then h' = dinv*h after k_scale
__device__ __half g_w1h[CH * CH];
__device__ unsigned g_pooled[NG * CH]; // reset to 0 by k_out

// ---------------- mma helpers ----------------------------------------------
__device__ __forceinline__ void ldsm_x4(uint32_t* r, uint32_t addr) {
    asm volatile("ldmatrix.sync.aligned.m8n8.x4.shared.b16 {%0,%1,%2,%3}, [%4];"
        : "=r"(r[0]), "=r"(r[1]), "=r"(r[2]), "=r"(r[3]) : "r"(addr));
}
__device__ __forceinline__ void ldsm_x4_t(uint32_t* r, uint32_t addr) {
    asm volatile("ldmatrix.sync.aligned.m8n8.x4.trans.shared.b16 {%0,%1,%2,%3}, [%4];"
        : "=r"(r[0]), "=r"(r[1]), "=r"(r[2]), "=r"(r[3]) : "r"(addr));
}
__device__ __forceinline__ void mma16816(float* d, const uint32_t* a, const uint32_t* b) {
    asm volatile("mma.sync.aligned.m16n8k16.row.col.f32.f16.f16.f32 "
        "{%0,%1,%2,%3}, {%4,%5,%6,%7}, {%8,%9}, {%0,%1,%2,%3};"
        : "+f"(d[0]), "+f"(d[1]), "+f"(d[2]), "+f"(d[3])
        : "r"(a[0]), "r"(a[1]), "r"(a[2]), "r"(a[3]), "r"(b[0]), "r"(b[1]));
}

// ---------------- prep: self-detecting dtype + scatter into buckets --------
__global__ void k_prep(const unsigned* __restrict__ ei,
                       const unsigned* __restrict__ bt) {
    __shared__ int s64e, s64b;
    {
        int w = threadIdx.x >> 5, lane = threadIdx.x & 31;
        if (w == 0) {
            unsigned v = ei[2 * lane * 999 + 1];     // odd 32-bit words
            unsigned m = __ballot_sync(0xffffffffu, v == 0u);
            if (lane == 0) s64e = (m == 0xffffffffu);
        } else if (w == 1) {
            unsigned v = bt[2001 + 2 * lane * 747];  // sorted batch, idx>2000
            unsigned m = __ballot_sync(0xffffffffu, v == 0u);
            if (lane == 0) s64b = (m == 0xffffffffu);
        }
    }
    __syncthreads();
    int t = blockIdx.x * blockDim.x + threadIdx.x;
    if (t < N_NODES / 2) {
        int b0, b1;
        if (s64b) {
            uint4 v = ((const uint4*)bt)[t];
            b0 = (int)v.x; b1 = (int)v.z;
        } else {
            uint2 v = ((const uint2*)bt)[t];
            b0 = (int)v.x; b1 = (int)v.y;
        }
        *(int2*)&g_batch[2 * t] = make_int2(b0, b1);
    }
    if (t >= N_EDGES / 2) return;
    int s0, s1, d0, d1;
    if (s64e) {
        uint4 a = ((const uint4*)ei)[t];
        uint4 b = ((const uint4*)ei)[N_EDGES / 2 + t];
        s0 = (int)a.x; s1 = (int)a.z;
        d0 = (int)b.x; d1 = (int)b.z;
    } else {
        uint2 a = ((const uint2*)ei)[t];
        uint2 b = ((const uint2*)ei)[N_EDGES / 2 + t];
        s0 = (int)a.x; s1 = (int)a.y;
        d0 = (int)b.x; d1 = (int)b.y;
    }
    int p0 = atomicAdd(&g_cursor[d0], 1);
    g_csr_src[d0 * CAP + min(p0, CAP - 1)] = s0;     // clamp: memory safety only
    int p1 = atomicAdd(&g_cursor[d1], 1);
    g_csr_src[d1 * CAP + min(p1, CAP - 1)] = s1;
}

// ---------------- W1 -> fp16 ----------------------------------------------
__global__ void k_wconv(const float* __restrict__ W1) {
    int t = blockIdx.x * blockDim.x + threadIdx.x;   // 4096 threads, 4 elems each
    float4 v = ((const float4*)W1)[t];
    __half2 h01 = __floats2half2_rn(v.x, v.y);
    __half2 h23 = __floats2half2_rn(v.z, v.w);
    ((uint2*)g_w1h)[t] = make_uint2(*(unsigned*)&h01, *(unsigned*)&h23);
}

// ---------------- h = x @ W1 via HMMA (fp16 in, fp32 accum, fp16 out) ------
__global__ void __launch_bounds__(128) k_gemm(const float* __restrict__ x) {
    extern __shared__ __half sm[];
    __half* As = sm;                 // [GM][LDA]
    __half* Bs = sm + GM * LDA;      // [CH][LDB]
    int tid = threadIdx.x;
    int row0 = blockIdx.x * GM;

#pragma unroll
    for (int i = 0; i < 16; i++) {
        int idx4 = tid + i * 128;                    // float4 index in 64x32
        int r = idx4 >> 5, c4 = idx4 & 31;
        int gr = row0 + r;
        float4 v = (gr < N_NODES) ? ((const float4*)x)[(size_t)gr * 32 + c4]
                                  : make_float4(0.f, 0.f, 0.f, 0.f);
        __half2 h01 = __floats2half2_rn(v.x, v.y);
        __half2 h23 = __floats2half2_rn(v.z, v.w);
        *(uint2*)&As[r * LDA + c4 * 4] = make_uint2(*(unsigned*)&h01, *(unsigned*)&h23);
    }
#pragma unroll
    for (int i = 0; i < 16; i++) {
        int idx8 = tid + i * 128;                    // uint4 index in 128x16
        int r = idx8 >> 4, c8 = idx8 & 15;
        *(uint4*)&Bs[r * LDB + c8 * 8] = ((const uint4*)g_w1h)[(size_t)r * 16 + c8];
    }
    __syncthreads();

    int w = tid >> 5, lane = tid & 31;
    int m0 = w * 16;
    uint32_t a_base = (uint32_t)__cvta_generic_to_shared(As)
                    + ((m0 + (lane & 15)) * LDA + (lane >> 4) * 8) * 2;
    uint32_t b_base = (uint32_t)__cvta_generic_to_shared(Bs)
                    + ((lane & 15) * LDB + (lane >> 4) * 8) * 2;

    float acc[16][4];
#pragma unroll
    for (int j = 0; j < 16; j++)
#pragma unroll
        for (int q = 0; q < 4; q++) acc[j][q] = 0.f;

#pragma unroll
    for (int kk = 0; kk < 8; kk++) {
        uint32_t a[4];
        ldsm_x4(a, a_base + kk * 16 * 2);
#pragma unroll
        for (int jt = 0; jt < 8; jt++) {
            uint32_t b[4];
            ldsm_x4_t(b, b_base + (kk * 16 * LDB + jt * 16) * 2);
            mma16816(acc[2 * jt], a, b);
            mma16816(acc[2 * jt + 1], a, b + 2);
        }
    }

    int r_lo = row0 + m0 + (lane >> 2);
    int r_hi = r_lo + 8;
    int cbase = (lane & 3) * 2;
#pragma unroll
    for (int j = 0; j < 16; j++) {
        int col = j * 8 + cbase;
        if (r_lo < N_NODES) {
            __half2 v = __floats2half2_rn(acc[j][0], acc[j][1]);
            *(unsigned*)&g_h[(size_t)r_lo * CH + col] = *(unsigned*)&v;
        }
        if (r_hi < N_NODES) {
            __half2 v = __floats2half2_rn(acc[j][2], acc[j][3]);
            *(unsigned*)&g_h[(size_t)r_hi * CH + col] = *(unsigned*)&v;
        }
    }
}

// ---------------- scale: h' = dinv * h, 2 nodes per warp (MLP=2) -----------
__global__ void __launch_bounds__(256) k_scale() {
    int w = threadIdx.x >> 5, lane = threadIdx.x & 31;
    int n0 = (blockIdx.x * 8 + w) * 2;               // 3125 blocks * 8 warps * 2
    if (n0 >= N_NODES) return;
    int c0 = g_cursor[n0], c1 = g_cursor[n0 + 1];
    float d0 = rsqrtf((float)(c0 + 1));
    float d1 = rsqrtf((float)(c1 + 1));
    uint2* r0 = (uint2*)&g_h[(size_t)n0 * CH];
    uint2* r1 = (uint2*)&g_h[(size_t)(n0 + 1) * CH];
    uint2 v0 = r0[lane];
    uint2 v1 = r1[lane];
    float2 a01 = __half22float2(*(__half2*)&v0.x);
    float2 a23 = __half22float2(*(__half2*)&v0.y);
    float2 b01 = __half22float2(*(__half2*)&v1.x);
    float2 b23 = __half22float2(*(__half2*)&v1.y);
    __half2 o0a = __floats2half2_rn(a01.x * d0, a01.y * d0);
    __half2 o0b = __floats2half2_rn(a23.x * d0, a23.y * d0);
    __half2 o1a = __floats2half2_rn(b01.x * d1, b01.y * d1);
    __half2 o1b = __floats2half2_rn(b23.x * d1, b23.y * d1);
    r0[lane] = make_uint2(*(unsigned*)&o0a, *(unsigned*)&o0b);
    r1[lane] = make_uint2(*(unsigned*)&o1a, *(unsigned*)&o1b);
}

// ---------------- aggregation + bias + relu + pooled max (fused) -----------
// h is pre-scaled; inner loop gathers and pairwise-adds edges in fp16
// (one HADD2 level) before fp32 accumulation: ~37% fewer math issue slots.
__global__ void __launch_bounds__(AGG_WARPS * 32) k_aggregate(
        const float* __restrict__ b1) {
    __shared__ float sval[AGG_WARPS * CH];
    __shared__ int sgid[AGG_WARPS];
    int tid = threadIdx.x;
    int w = tid >> 5, lane = tid & 31;
    int d = blockIdx.x * AGG_WARPS + w;              // < N_NODES (50000 % 16 == 0)

    int cnt_d = g_cursor[d];
    float di = rsqrtf((float)(cnt_d + 1));
    const uint2* __restrict__ h2 = (const uint2*)g_h;

    uint2 hs = h2[(size_t)d * 32 + lane];            // self loop (pre-scaled)
    float2 s01 = __half22float2(*(__half2*)&hs.x);
    float2 s23 = __half22float2(*(__half2*)&hs.y);
    float ax = s01.x, ay = s01.y, az = s23.x, aw = s23.y;

    int e0 = d * CAP;
    int e1 = e0 + min(cnt_d, CAP);
    int e = e0;
    for (; e + 3 < e1; e += 4) {
        int sA = g_csr_src[e],     sB = g_csr_src[e + 1];
        int sC = g_csr_src[e + 2], sD = g_csr_src[e + 3];
        uint2 hA = h2[(size_t)sA * 32 + lane];
        uint2 hB = h2[(size_t)sB * 32 + lane];
        uint2 hC = h2[(size_t)sC * 32 + lane];
        uint2 hD = h2[(size_t)sD * 32 + lane];
        // pairwise fp16 pre-add (one rounding per pair), then fp32 accumulate
        __half2 pABx = __hadd2(*(__half2*)&hA.x, *(__half2*)&hB.x);
        __half2 pCDx = __hadd2(*(__half2*)&hC.x, *(__half2*)&hD.x);
        __half2 pABy = __hadd2(*(__half2*)&hA.y, *(__half2*)&hB.y);
        __half2 pCDy = __hadd2(*(__half2*)&hC.y, *(__half2*)&hD.y);
        float2 fABx = __half22float2(pABx);
        float2 fCDx = __half22float2(pCDx);
        float2 fABy = __half22float2(pABy);
        float2 fCDy = __half22float2(pCDy);
        ax += fABx.x + fCDx.x;
        ay += fABx.y + fCDx.y;
        az += fABy.x + fCDy.x;
        aw += fABy.y + fCDy.y;
    }
    for (; e < e1; e++) {
        int sA = g_csr_src[e];
        uint2 hA = h2[(size_t)sA * 32 + lane];
        float2 a01 = __half22float2(*(__half2*)&hA.x);
        float2 a23 = __half22float2(*(__half2*)&hA.y);
        ax += a01.x; ay += a01.y; az += a23.x; aw += a23.y;
    }

    float4 bb = *(const float4*)&b1[lane * 4];
    float4 v;
    v.x = fmaxf(fmaf(ax, di, bb.x), 0.f);
    v.y = fmaxf(fmaf(ay, di, bb.y), 0.f);
    v.z = fmaxf(fmaf(az, di, bb.z), 0.f);
    v.w = fmaxf(fmaf(aw, di, bb.w), 0.f);
    *(float4*)&sval[w * CH + lane * 4] = v;
    if (lane == 0) sgid[w] = g_batch[d];
    __syncthreads();

    if (tid < CH) {
        int c = tid;
        int curg = sgid[0];
        float m = sval[c];
        for (int ww = 1; ww < AGG_WARPS; ww++) {
            int g = sgid[ww];
            float u = sval[ww * CH + c];
            if (g == curg) {
                m = fmaxf(m, u);
            } else {
                atomicMax(&g_pooled[curg * CH + c], __float_as_uint(m));
                curg = g; m = u;
            }
        }
        atomicMax(&g_pooled[curg * CH + c], __float_as_uint(m));
    }
}

// ---------------- out = relu(pooled @ W2 + b2); restore invariants ---------
__global__ void k_out(const float* __restrict__ W2, const float* __restrict__ b2,
                      float* __restrict__ out) {
    __shared__ float p[CH];
    int g = blockIdx.x, c = threadIdx.x;
    p[c]      = __uint_as_float(g_pooled[g * CH + c]);
    p[c + 64] = __uint_as_float(g_pooled[g * CH + c + 64]);
    __syncthreads();
    // restore zero-invariants for the next replay
    g_pooled[g * CH + c] = 0u;
    g_pooled[g * CH + c + 64] = 0u;
    {   // block g zeroes cursor slice [g*196, g*196+196) ∩ [0, N_NODES)
        int base = g * 196;
        for (int i = c; i < 196; i += OUTC) {
            int idx = base + i;
            if (idx < N_NODES) g_cursor[idx] = 0;
        }
    }
    float acc = b2[c];
#pragma unroll 8
    for (int k = 0; k < CH; k++)
        acc = fmaf(p[k], W2[k * OUTC + c], acc);
    out[g * OUTC + c] = fmaxf(acc, 0.f);
}

// ---------------- launch ---------------------------------------------------
extern "C" void kernel_launch(void* const* d_in, const int* in_sizes, int n_in,
                              void* d_out, int out_size) {
    const float *x = nullptr, *W1 = nullptr, *b1 = nullptr, *W2 = nullptr, *b2 = nullptr;
    const unsigned *ei = nullptr, *bt = nullptr;
    for (int i = 0; i < n_in; i++) {
        switch (in_sizes[i]) {
            case N_NODES * CH:    x  = (const float*)d_in[i]; break;
            case 2 * N_EDGES:     ei = (const unsigned*)d_in[i]; break;
            case N_NODES:         bt = (const unsigned*)d_in[i]; break;
            case CH * CH:         W1 = (const float*)d_in[i]; break;
            case CH:              b1 = (const float*)d_in[i]; break;
            case CH * OUTC:       W2 = (const float*)d_in[i]; break;
            case OUTC:            b2 = (const float*)d_in[i]; break;
        }
    }
    float* out = (float*)d_out;

    static cudaStream_t sB = nullptr;
    static cudaEvent_t evFork = nullptr, evJoin = nullptr;
    if (!sB) {
        cudaStreamCreateWithFlags(&sB, cudaStreamNonBlocking);
        cudaEventCreateWithFlags(&evFork, cudaEventDisableTiming);
        cudaEventCreateWithFlags(&evJoin, cudaEventDisableTiming);
        cudaFuncSetAttribute(k_gemm, cudaFuncAttributeMaxDynamicSharedMemorySize,
                             GEMM_SMEM);
    }

    // Fork: W-convert + tensor-core GEMM overlap the edge preprocessing.
    cudaEventRecord(evFork, 0);
    cudaStreamWaitEvent(sB, evFork, 0);
    k_wconv<<<16, 256, 0, sB>>>(W1);
    k_gemm<<<(N_NODES + GM - 1) / GM, 128, GEMM_SMEM, sB>>>(x);
    cudaEventRecord(evJoin, sB);

    // Main: prep, join gemm, scale h in place, aggregate, out.
    k_prep<<<(N_EDGES / 2 + 255) / 256, 256>>>(ei, bt);
    cudaStreamWaitEvent(0, evJoin, 0);               // h must exist for k_scale
    k_scale<<<N_NODES / 16, 256>>>();
    k_aggregate<<<N_NODES / AGG_WARPS, AGG_WARPS * 32>>>(b1);
    k_out<<<NG, OUTC>>>(W2, b2, out);
}

// round 15
// speedup vs baseline: 1.0966x; 1.0166x over previous
#include <cuda_runtime.h>
#include <cuda_fp16.h>
#include <cstdint>

#define N_NODES 50000
#define N_EDGES 800000
#define CH 128
#define OUTC 64
#define NG 256
#define CAP 128                 // bucket capacity per node

#define AGG_WARPS 16

// GEMM tiling: 64 rows x 128 cols per block, 4 warps, mma.m16n8k16
#define GM 64
#define LDA 136                  // halves, 272B rows -> conflict-free ldmatrix
#define LDB 136
#define GEMM_SMEM ((GM * LDA + CH * LDB) * 2)

// ---------------- scratch (device globals; no allocation allowed) ----------
// INVARIANT: g_cursor and g_pooled are all-zero before each kernel_launch
// (zero-init at load; k_out restores zero afterwards).
__device__ int g_csr_src[N_NODES * CAP];
__device__ int g_cursor[N_NODES];      // in-degree per node; reset by k_out
__device__ int g_batch[N_NODES];
__device__ __half g_h[(size_t)N_NODES * CH];   // h, then h' = dinv*h after k_scale
__device__ __half g_w1h[CH * CH];
__device__ unsigned g_pooled[NG * CH]; // reset to 0 by k_out

// ---------------- mma helpers ----------------------------------------------
__device__ __forceinline__ void ldsm_x4(uint32_t* r, uint32_t addr) {
    asm volatile("ldmatrix.sync.aligned.m8n8.x4.shared.b16 {%0,%1,%2,%3}, [%4];"
        : "=r"(r[0]), "=r"(r[1]), "=r"(r[2]), "=r"(r[3]) : "r"(addr));
}
__device__ __forceinline__ void ldsm_x4_t(uint32_t* r, uint32_t addr) {
    asm volatile("ldmatrix.sync.aligned.m8n8.x4.trans.shared.b16 {%0,%1,%2,%3}, [%4];"
        : "=r"(r[0]), "=r"(r[1]), "=r"(r[2]), "=r"(r[3]) : "r"(addr));
}
__device__ __forceinline__ void mma16816(float* d, const uint32_t* a, const uint32_t* b) {
    asm volatile("mma.sync.aligned.m16n8k16.row.col.f32.f16.f16.f32 "
        "{%0,%1,%2,%3}, {%4,%5,%6,%7}, {%8,%9}, {%0,%1,%2,%3};"
        : "+f"(d[0]), "+f"(d[1]), "+f"(d[2]), "+f"(d[3])
        : "r"(a[0]), "r"(a[1]), "r"(a[2]), "r"(a[3]), "r"(b[0]), "r"(b[1]));
}

// ---------------- prep: edges only — self-detecting dtype + scatter --------
__global__ void k_prep(const unsigned* __restrict__ ei) {
    __shared__ int s64e;
    {
        int w = threadIdx.x >> 5, lane = threadIdx.x & 31;
        if (w == 0) {
            unsigned v = ei[2 * lane * 999 + 1];     // odd 32-bit words
            unsigned m = __ballot_sync(0xffffffffu, v == 0u);
            if (lane == 0) s64e = (m == 0xffffffffu);
        }
    }
    __syncthreads();
    int t = blockIdx.x * blockDim.x + threadIdx.x;
    if (t >= N_EDGES / 2) return;
    int s0, s1, d0, d1;
    if (s64e) {
        uint4 a = ((const uint4*)ei)[t];
        uint4 b = ((const uint4*)ei)[N_EDGES / 2 + t];
        s0 = (int)a.x; s1 = (int)a.z;
        d0 = (int)b.x; d1 = (int)b.z;
    } else {
        uint2 a = ((const uint2*)ei)[t];
        uint2 b = ((const uint2*)ei)[N_EDGES / 2 + t];
        s0 = (int)a.x; s1 = (int)a.y;
        d0 = (int)b.x; d1 = (int)b.y;
    }
    int p0 = atomicAdd(&g_cursor[d0], 1);
    g_csr_src[d0 * CAP + min(p0, CAP - 1)] = s0;     // clamp: memory safety only
    int p1 = atomicAdd(&g_cursor[d1], 1);
    g_csr_src[d1 * CAP + min(p1, CAP - 1)] = s1;
}

// ---------------- W1 -> fp16 + batch conversion (side stream) --------------
__global__ void k_wconv(const float* __restrict__ W1,
                        const unsigned* __restrict__ bt) {
    __shared__ int s64b;
    {
        int w = threadIdx.x >> 5, lane = threadIdx.x & 31;
        if (w == 0) {
            unsigned v = bt[2001 + 2 * lane * 747];  // sorted batch, idx>2000
            unsigned m = __ballot_sync(0xffffffffu, v == 0u);
            if (lane == 0) s64b = (m == 0xffffffffu);
        }
    }
    __syncthreads();
    int t = blockIdx.x * blockDim.x + threadIdx.x;   // 4096 threads
    {   // W1 fp32 -> fp16, 4 elems each
        float4 v = ((const float4*)W1)[t];
        __half2 h01 = __floats2half2_rn(v.x, v.y);
        __half2 h23 = __floats2half2_rn(v.z, v.w);
        ((uint2*)g_w1h)[t] = make_uint2(*(unsigned*)&h01, *(unsigned*)&h23);
    }
    // batch conversion: 25000 pairs over 4096 threads
    for (int i = t; i < N_NODES / 2; i += 4096) {
        int b0, b1;
        if (s64b) {
            uint4 v = ((const uint4*)bt)[i];
            b0 = (int)v.x; b1 = (int)v.z;
        } else {
            uint2 v = ((const uint2*)bt)[i];
            b0 = (int)v.x; b1 = (int)v.y;
        }
        *(int2*)&g_batch[2 * i] = make_int2(b0, b1);
    }
}

// ---------------- h = x @ W1 via HMMA (fp16 in, fp32 accum, fp16 out) ------
__global__ void __launch_bounds__(128) k_gemm(const float* __restrict__ x) {
    extern __shared__ __half sm[];
    __half* As = sm;                 // [GM][LDA]
    __half* Bs = sm + GM * LDA;      // [CH][LDB]
    int tid = threadIdx.x;
    int row0 = blockIdx.x * GM;

#pragma unroll
    for (int i = 0; i < 16; i++) {
        int idx4 = tid + i * 128;                    // float4 index in 64x32
        int r = idx4 >> 5, c4 = idx4 & 31;
        int gr = row0 + r;
        float4 v = (gr < N_NODES) ? ((const float4*)x)[(size_t)gr * 32 + c4]
                                  : make_float4(0.f, 0.f, 0.f, 0.f);
        __half2 h01 = __floats2half2_rn(v.x, v.y);
        __half2 h23 = __floats2half2_rn(v.z, v.w);
        *(uint2*)&As[r * LDA + c4 * 4] = make_uint2(*(unsigned*)&h01, *(unsigned*)&h23);
    }
#pragma unroll
    for (int i = 0; i < 16; i++) {
        int idx8 = tid + i * 128;                    // uint4 index in 128x16
        int r = idx8 >> 4, c8 = idx8 & 15;
        *(uint4*)&Bs[r * LDB + c8 * 8] = ((const uint4*)g_w1h)[(size_t)r * 16 + c8];
    }
    __syncthreads();

    int w = tid >> 5, lane = tid & 31;
    int m0 = w * 16;
    uint32_t a_base = (uint32_t)__cvta_generic_to_shared(As)
                    + ((m0 + (lane & 15)) * LDA + (lane >> 4) * 8) * 2;
    uint32_t b_base = (uint32_t)__cvta_generic_to_shared(Bs)
                    + ((lane & 15) * LDB + (lane >> 4) * 8) * 2;

    float acc[16][4];
#pragma unroll
    for (int j = 0; j < 16; j++)
#pragma unroll
        for (int q = 0; q < 4; q++) acc[j][q] = 0.f;

#pragma unroll
    for (int kk = 0; kk < 8; kk++) {
        uint32_t a[4];
        ldsm_x4(a, a_base + kk * 16 * 2);
#pragma unroll
        for (int jt = 0; jt < 8; jt++) {
            uint32_t b[4];
            ldsm_x4_t(b, b_base + (kk * 16 * LDB + jt * 16) * 2);
            mma16816(acc[2 * jt], a, b);
            mma16816(acc[2 * jt + 1], a, b + 2);
        }
    }

    int r_lo = row0 + m0 + (lane >> 2);
    int r_hi = r_lo + 8;
    int cbase = (lane & 3) * 2;
#pragma unroll
    for (int j = 0; j < 16; j++) {
        int col = j * 8 + cbase;
        if (r_lo < N_NODES) {
            __half2 v = __floats2half2_rn(acc[j][0], acc[j][1]);
            *(unsigned*)&g_h[(size_t)r_lo * CH + col] = *(unsigned*)&v;
        }
        if (r_hi < N_NODES) {
            __half2 v = __floats2half2_rn(acc[j][2], acc[j][3]);
            *(unsigned*)&g_h[(size_t)r_hi * CH + col] = *(unsigned*)&v;
        }
    }
}

// ---------------- scale: h' = dinv * h, 4 nodes per warp (MLP=4) -----------
__global__ void __launch_bounds__(256) k_scale() {
    int w = threadIdx.x >> 5, lane = threadIdx.x & 31;
    int n0 = (blockIdx.x * 8 + w) * 4;               // 1563 blocks * 8 warps * 4
    if (n0 >= N_NODES) return;
    uint2 v[4];
    float di[4];
    uint2* rows[4];
#pragma unroll
    for (int i = 0; i < 4; i++) {
        int n = n0 + i;
        bool ok = (n < N_NODES);
        int cnt = ok ? g_cursor[n] : 0;
        di[i] = rsqrtf((float)(cnt + 1));
        rows[i] = (uint2*)&g_h[(size_t)(ok ? n : 0) * CH];
        v[i] = rows[i][lane];
    }
#pragma unroll
    for (int i = 0; i < 4; i++) {
        int n = n0 + i;
        if (n >= N_NODES) break;
        float2 f01 = __half22float2(*(__half2*)&v[i].x);
        float2 f23 = __half22float2(*(__half2*)&v[i].y);
        __half2 oa = __floats2half2_rn(f01.x * di[i], f01.y * di[i]);
        __half2 ob = __floats2half2_rn(f23.x * di[i], f23.y * di[i]);
        rows[i][lane] = make_uint2(*(unsigned*)&oa, *(unsigned*)&ob);
    }
}

// ---------------- aggregation + bias + relu + pooled max (fused) -----------
// h is pre-scaled; inner loop gathers and pairwise-adds edges in fp16
// (one HADD2 level) before fp32 accumulation.
__global__ void __launch_bounds__(AGG_WARPS * 32) k_aggregate(
        const float* __restrict__ b1) {
    __shared__ float sval[AGG_WARPS * CH];
    __shared__ int sgid[AGG_WARPS];
    int tid = threadIdx.x;
    int w = tid >> 5, lane = tid & 31;
    int d = blockIdx.x * AGG_WARPS + w;              // < N_NODES (50000 % 16 == 0)

    int cnt_d = g_cursor[d];
    float di = rsqrtf((float)(cnt_d + 1));
    const uint2* __restrict__ h2 = (const uint2*)g_h;

    uint2 hs = h2[(size_t)d * 32 + lane];            // self loop (pre-scaled)
    float2 s01 = __half22float2(*(__half2*)&hs.x);
    float2 s23 = __half22float2(*(__half2*)&hs.y);
    float ax = s01.x, ay = s01.y, az = s23.x, aw = s23.y;

    int e0 = d * CAP;
    int e1 = e0 + min(cnt_d, CAP);
    int e = e0;
    for (; e + 3 < e1; e += 4) {
        int sA = g_csr_src[e],     sB = g_csr_src[e + 1];
        int sC = g_csr_src[e + 2], sD = g_csr_src[e + 3];
        uint2 hA = h2[(size_t)sA * 32 + lane];
        uint2 hB = h2[(size_t)sB * 32 + lane];
        uint2 hC = h2[(size_t)sC * 32 + lane];
        uint2 hD = h2[(size_t)sD * 32 + lane];
        __half2 pABx = __hadd2(*(__half2*)&hA.x, *(__half2*)&hB.x);
        __half2 pCDx = __hadd2(*(__half2*)&hC.x, *(__half2*)&hD.x);
        __half2 pABy = __hadd2(*(__half2*)&hA.y, *(__half2*)&hB.y);
        __half2 pCDy = __hadd2(*(__half2*)&hC.y, *(__half2*)&hD.y);
        float2 fABx = __half22float2(pABx);
        float2 fCDx = __half22float2(pCDx);
        float2 fABy = __half22float2(pABy);
        float2 fCDy = __half22float2(pCDy);
        ax += fABx.x + fCDx.x;
        ay += fABx.y + fCDx.y;
        az += fABy.x + fCDy.x;
        aw += fABy.y + fCDy.y;
    }
    for (; e < e1; e++) {
        int sA = g_csr_src[e];
        uint2 hA = h2[(size_t)sA * 32 + lane];
        float2 a01 = __half22float2(*(__half2*)&hA.x);
        float2 a23 = __half22float2(*(__half2*)&hA.y);
        ax += a01.x; ay += a01.y; az += a23.x; aw += a23.y;
    }

    float4 bb = *(const float4*)&b1[lane * 4];
    float4 v;
    v.x = fmaxf(fmaf(ax, di, bb.x), 0.f);
    v.y = fmaxf(fmaf(ay, di, bb.y), 0.f);
    v.z = fmaxf(fmaf(az, di, bb.z), 0.f);
    v.w = fmaxf(fmaf(aw, di, bb.w), 0.f);
    *(float4*)&sval[w * CH + lane * 4] = v;
    if (lane == 0) sgid[w] = g_batch[d];
    __syncthreads();

    if (tid < CH) {
        int c = tid;
        int curg = sgid[0];
        float m = sval[c];
        for (int ww = 1; ww < AGG_WARPS; ww++) {
            int g = sgid[ww];
            float u = sval[ww * CH + c];
            if (g == curg) {
                m = fmaxf(m, u);
            } else {
                atomicMax(&g_pooled[curg * CH + c], __float_as_uint(m));
                curg = g; m = u;
            }
        }
        atomicMax(&g_pooled[curg * CH + c], __float_as_uint(m));
    }
}

// ---------------- out = relu(pooled @ W2 + b2); restore invariants ---------
__global__ void k_out(const float* __restrict__ W2, const float* __restrict__ b2,
                      float* __restrict__ out) {
    __shared__ float p[CH];
    int g = blockIdx.x, c = threadIdx.x;
    p[c]      = __uint_as_float(g_pooled[g * CH + c]);
    p[c + 64] = __uint_as_float(g_pooled[g * CH + c + 64]);
    __syncthreads();
    // restore zero-invariants for the next replay
    g_pooled[g * CH + c] = 0u;
    g_pooled[g * CH + c + 64] = 0u;
    {   // block g zeroes cursor slice [g*196, g*196+196) ∩ [0, N_NODES)
        int base = g * 196;
        for (int i = c; i < 196; i += OUTC) {
            int idx = base + i;
            if (idx < N_NODES) g_cursor[idx] = 0;
        }
    }
    float acc = b2[c];
#pragma unroll 8
    for (int k = 0; k < CH; k++)
        acc = fmaf(p[k], W2[k * OUTC + c], acc);
    out[g * OUTC + c] = fmaxf(acc, 0.f);
}

// ---------------- launch ---------------------------------------------------
extern "C" void kernel_launch(void* const* d_in, const int* in_sizes, int n_in,
                              void* d_out, int out_size) {
    const float *x = nullptr, *W1 = nullptr, *b1 = nullptr, *W2 = nullptr, *b2 = nullptr;
    const unsigned *ei = nullptr, *bt = nullptr;
    for (int i = 0; i < n_in; i++) {
        switch (in_sizes[i]) {
            case N_NODES * CH:    x  = (const float*)d_in[i]; break;
            case 2 * N_EDGES:     ei = (const unsigned*)d_in[i]; break;
            case N_NODES:         bt = (const unsigned*)d_in[i]; break;
            case CH * CH:         W1 = (const float*)d_in[i]; break;
            case CH:              b1 = (const float*)d_in[i]; break;
            case CH * OUTC:       W2 = (const float*)d_in[i]; break;
            case OUTC:            b2 = (const float*)d_in[i]; break;
        }
    }
    float* out = (float*)d_out;

    static cudaStream_t sB = nullptr;
    static cudaEvent_t evFork = nullptr, evJoin = nullptr;
    if (!sB) {
        cudaStreamCreateWithFlags(&sB, cudaStreamNonBlocking);
        cudaEventCreateWithFlags(&evFork, cudaEventDisableTiming);
        cudaEventCreateWithFlags(&evJoin, cudaEventDisableTiming);
        cudaFuncSetAttribute(k_gemm, cudaFuncAttributeMaxDynamicSharedMemorySize,
                             GEMM_SMEM);
    }

    // Fork: W-convert+batch (side) + tensor-core GEMM overlap edge prep.
    cudaEventRecord(evFork, 0);
    cudaStreamWaitEvent(sB, evFork, 0);
    k_wconv<<<16, 256, 0, sB>>>(W1, bt);
    k_gemm<<<(N_NODES + GM - 1) / GM, 128, GEMM_SMEM, sB>>>(x);
    cudaEventRecord(evJoin, sB);

    // Main: prep (edges only), join gemm, scale h in place, aggregate, out.
    k_prep<<<(N_EDGES / 2 + 255) / 256, 256>>>(ei);
    cudaStreamWaitEvent(0, evJoin, 0);               // h must exist for k_scale
    k_scale<<<(N_NODES + 31) / 32, 256>>>();
    k_aggregate<<<N_NODES / AGG_WARPS, AGG_WARPS * 32>>>(b1);
    k_out<<<NG, OUTC>>>(W2, b2, out);
}

// round 16
// speedup vs baseline: 1.1296x; 1.0302x over previous
#include <cuda_runtime.h>
#include <cuda_fp16.h>
#include <cstdint>

#define N_NODES 50000
#define N_EDGES 800000
#define CH 128
#define OUTC 64
#define NG 256
#define CAP 128                 // bucket capacity per node

#define AGG_WARPS 16

// GEMM tiling: 64 rows x 128 cols per block, 4 warps, mma.m16n8k16
#define GM 64
#define LDA 136                  // halves, 272B rows -> conflict-free ldmatrix
#define LDB 136
#define GEMM_SMEM ((GM * LDA + CH * LDB) * 2)

// ---------------- scratch (device globals; no allocation allowed) ----------
// INVARIANT: g_cursor and g_pooled are all-zero before each kernel_launch
// (zero-init at load; k_out restores zero afterwards).
__device__ int g_csr_src[N_NODES * CAP];
__device__ int g_cursor[N_NODES];      // in-degree per node; reset by k_out
__device__ int g_batch[N_NODES];
__device__ __half g_h[(size_t)N_NODES * CH];   // h, then h' = dinv*h after k_scale
__device__ __half g_w1h[CH * CH];
__device__ unsigned g_pooled[NG * CH]; // reset to 0 by k_out

// ---------------- mma helpers ----------------------------------------------
__device__ __forceinline__ void ldsm_x4(uint32_t* r, uint32_t addr) {
    asm volatile("ldmatrix.sync.aligned.m8n8.x4.shared.b16 {%0,%1,%2,%3}, [%4];"
        : "=r"(r[0]), "=r"(r[1]), "=r"(r[2]), "=r"(r[3]) : "r"(addr));
}
__device__ __forceinline__ void ldsm_x4_t(uint32_t* r, uint32_t addr) {
    asm volatile("ldmatrix.sync.aligned.m8n8.x4.trans.shared.b16 {%0,%1,%2,%3}, [%4];"
        : "=r"(r[0]), "=r"(r[1]), "=r"(r[2]), "=r"(r[3]) : "r"(addr));
}
__device__ __forceinline__ void mma16816(float* d, const uint32_t* a, const uint32_t* b) {
    asm volatile("mma.sync.aligned.m16n8k16.row.col.f32.f16.f16.f32 "
        "{%0,%1,%2,%3}, {%4,%5,%6,%7}, {%8,%9}, {%0,%1,%2,%3};"
        : "+f"(d[0]), "+f"(d[1]), "+f"(d[2]), "+f"(d[3])
        : "r"(a[0]), "r"(a[1]), "r"(a[2]), "r"(a[3]), "r"(b[0]), "r"(b[1]));
}

// ---------------- prep: edges only — self-detecting dtype + scatter --------
__global__ void k_prep(const unsigned* __restrict__ ei) {
    __shared__ int s64e;
    {
        int w = threadIdx.x >> 5, lane = threadIdx.x & 31;
        if (w == 0) {
            unsigned v = ei[2 * lane * 999 + 1];     // odd 32-bit words
            unsigned m = __ballot_sync(0xffffffffu, v == 0u);
            if (lane == 0) s64e = (m == 0xffffffffu);
        }
    }
    __syncthreads();
    int t = blockIdx.x * blockDim.x + threadIdx.x;
    if (t >= N_EDGES / 2) return;
    int s0, s1, d0, d1;
    if (s64e) {
        uint4 a = ((const uint4*)ei)[t];
        uint4 b = ((const uint4*)ei)[N_EDGES / 2 + t];
        s0 = (int)a.x; s1 = (int)a.z;
        d0 = (int)b.x; d1 = (int)b.z;
    } else {
        uint2 a = ((const uint2*)ei)[t];
        uint2 b = ((const uint2*)ei)[N_EDGES / 2 + t];
        s0 = (int)a.x; s1 = (int)a.y;
        d0 = (int)b.x; d1 = (int)b.y;
    }
    int p0 = atomicAdd(&g_cursor[d0], 1);
    g_csr_src[d0 * CAP + min(p0, CAP - 1)] = s0;     // clamp: memory safety only
    int p1 = atomicAdd(&g_cursor[d1], 1);
    g_csr_src[d1 * CAP + min(p1, CAP - 1)] = s1;
}

// ---------------- W1 -> fp16 + batch conversion (side stream) --------------
__global__ void k_wconv(const float* __restrict__ W1,
                        const unsigned* __restrict__ bt) {
    __shared__ int s64b;
    {
        int w = threadIdx.x >> 5, lane = threadIdx.x & 31;
        if (w == 0) {
            unsigned v = bt[2001 + 2 * lane * 747];  // sorted batch, idx>2000
            unsigned m = __ballot_sync(0xffffffffu, v == 0u);
            if (lane == 0) s64b = (m == 0xffffffffu);
        }
    }
    __syncthreads();
    int t = blockIdx.x * blockDim.x + threadIdx.x;   // 4096 threads
    {   // W1 fp32 -> fp16, 4 elems each
        float4 v = ((const float4*)W1)[t];
        __half2 h01 = __floats2half2_rn(v.x, v.y);
        __half2 h23 = __floats2half2_rn(v.z, v.w);
        ((uint2*)g_w1h)[t] = make_uint2(*(unsigned*)&h01, *(unsigned*)&h23);
    }
    // batch conversion: 25000 pairs over 4096 threads
    for (int i = t; i < N_NODES / 2; i += 4096) {
        int b0, b1;
        if (s64b) {
            uint4 v = ((const uint4*)bt)[i];
            b0 = (int)v.x; b1 = (int)v.z;
        } else {
            uint2 v = ((const uint2*)bt)[i];
            b0 = (int)v.x; b1 = (int)v.y;
        }
        *(int2*)&g_batch[2 * i] = make_int2(b0, b1);
    }
}

// ---------------- h = x @ W1 via HMMA (fp16 in, fp32 accum, fp16 out) ------
__global__ void __launch_bounds__(128) k_gemm(const float* __restrict__ x) {
    extern __shared__ __half sm[];
    __half* As = sm;                 // [GM][LDA]
    __half* Bs = sm + GM * LDA;      // [CH][LDB]
    int tid = threadIdx.x;
    int row0 = blockIdx.x * GM;

#pragma unroll
    for (int i = 0; i < 16; i++) {
        int idx4 = tid + i * 128;                    // float4 index in 64x32
        int r = idx4 >> 5, c4 = idx4 & 31;
        int gr = row0 + r;
        float4 v = (gr < N_NODES) ? ((const float4*)x)[(size_t)gr * 32 + c4]
                                  : make_float4(0.f, 0.f, 0.f, 0.f);
        __half2 h01 = __floats2half2_rn(v.x, v.y);
        __half2 h23 = __floats2half2_rn(v.z, v.w);
        *(uint2*)&As[r * LDA + c4 * 4] = make_uint2(*(unsigned*)&h01, *(unsigned*)&h23);
    }
#pragma unroll
    for (int i = 0; i < 16; i++) {
        int idx8 = tid + i * 128;                    // uint4 index in 128x16
        int r = idx8 >> 4, c8 = idx8 & 15;
        *(uint4*)&Bs[r * LDB + c8 * 8] = ((const uint4*)g_w1h)[(size_t)r * 16 + c8];
    }
    __syncthreads();

    int w = tid >> 5, lane = tid & 31;
    int m0 = w * 16;
    uint32_t a_base = (uint32_t)__cvta_generic_to_shared(As)
                    + ((m0 + (lane & 15)) * LDA + (lane >> 4) * 8) * 2;
    uint32_t b_base = (uint32_t)__cvta_generic_to_shared(Bs)
                    + ((lane & 15) * LDB + (lane >> 4) * 8) * 2;

    float acc[16][4];
#pragma unroll
    for (int j = 0; j < 16; j++)
#pragma unroll
        for (int q = 0; q < 4; q++) acc[j][q] = 0.f;

#pragma unroll
    for (int kk = 0; kk < 8; kk++) {
        uint32_t a[4];
        ldsm_x4(a, a_base + kk * 16 * 2);
#pragma unroll
        for (int jt = 0; jt < 8; jt++) {
            uint32_t b[4];
            ldsm_x4_t(b, b_base + (kk * 16 * LDB + jt * 16) * 2);
            mma16816(acc[2 * jt], a, b);
            mma16816(acc[2 * jt + 1], a, b + 2);
        }
    }

    int r_lo = row0 + m0 + (lane >> 2);
    int r_hi = r_lo + 8;
    int cbase = (lane & 3) * 2;
#pragma unroll
    for (int j = 0; j < 16; j++) {
        int col = j * 8 + cbase;
        if (r_lo < N_NODES) {
            __half2 v = __floats2half2_rn(acc[j][0], acc[j][1]);
            *(unsigned*)&g_h[(size_t)r_lo * CH + col] = *(unsigned*)&v;
        }
        if (r_hi < N_NODES) {
            __half2 v = __floats2half2_rn(acc[j][2], acc[j][3]);
            *(unsigned*)&g_h[(size_t)r_hi * CH + col] = *(unsigned*)&v;
        }
    }
}

// ---------------- scale: h' = dinv * h, 8 nodes per warp (MLP=8) -----------
__global__ void __launch_bounds__(256) k_scale() {
    int w = threadIdx.x >> 5, lane = threadIdx.x & 31;
    int n0 = (blockIdx.x * 8 + w) * 8;               // 782 blocks * 8 warps * 8
    if (n0 >= N_NODES) return;
    uint2 v[8];
    float di[8];
    uint2* rows[8];
#pragma unroll
    for (int i = 0; i < 8; i++) {
        int n = n0 + i;
        bool ok = (n < N_NODES);
        int cnt = ok ? g_cursor[n] : 0;
        di[i] = rsqrtf((float)(cnt + 1));
        rows[i] = (uint2*)&g_h[(size_t)(ok ? n : 0) * CH];
        v[i] = rows[i][lane];
    }
#pragma unroll
    for (int i = 0; i < 8; i++) {
        int n = n0 + i;
        if (n >= N_NODES) break;
        float2 f01 = __half22float2(*(__half2*)&v[i].x);
        float2 f23 = __half22float2(*(__half2*)&v[i].y);
        __half2 oa = __floats2half2_rn(f01.x * di[i], f01.y * di[i]);
        __half2 ob = __floats2half2_rn(f23.x * di[i], f23.y * di[i]);
        rows[i][lane] = make_uint2(*(unsigned*)&oa, *(unsigned*)&ob);
    }
}

// ---------------- aggregation + bias + relu + pooled max (fused) -----------
// h is pre-scaled; unroll-8 inner loop keeps 8 gathers in flight with one
// fp16 pairwise pre-add level (same per-edge rounding depth as R14).
__global__ void __launch_bounds__(AGG_WARPS * 32) k_aggregate(
        const float* __restrict__ b1) {
    __shared__ float sval[AGG_WARPS * CH];
    __shared__ int sgid[AGG_WARPS];
    int tid = threadIdx.x;
    int w = tid >> 5, lane = tid & 31;
    int d = blockIdx.x * AGG_WARPS + w;              // < N_NODES (50000 % 16 == 0)

    int cnt_d = g_cursor[d];
    float di = rsqrtf((float)(cnt_d + 1));
    const uint2* __restrict__ h2 = (const uint2*)g_h;

    uint2 hs = h2[(size_t)d * 32 + lane];            // self loop (pre-scaled)
    float2 s01 = __half22float2(*(__half2*)&hs.x);
    float2 s23 = __half22float2(*(__half2*)&hs.y);
    float ax = s01.x, ay = s01.y, az = s23.x, aw = s23.y;

    int e0 = d * CAP;
    int e1 = e0 + min(cnt_d, CAP);
    int e = e0;
    for (; e + 7 < e1; e += 8) {
        int si[8];
#pragma unroll
        for (int i = 0; i < 8; i++) si[i] = g_csr_src[e + i];
        uint2 hv[8];
#pragma unroll
        for (int i = 0; i < 8; i++) hv[i] = h2[(size_t)si[i] * 32 + lane];
#pragma unroll
        for (int p = 0; p < 4; p++) {                // pairs (0,1)(2,3)(4,5)(6,7)
            __half2 px = __hadd2(*(__half2*)&hv[2 * p].x, *(__half2*)&hv[2 * p + 1].x);
            __half2 py = __hadd2(*(__half2*)&hv[2 * p].y, *(__half2*)&hv[2 * p + 1].y);
            float2 fx = __half22float2(px);
            float2 fy = __half22float2(py);
            ax += fx.x; ay += fx.y; az += fy.x; aw += fy.y;
        }
    }
    for (; e + 3 < e1; e += 4) {
        int sA = g_csr_src[e],     sB = g_csr_src[e + 1];
        int sC = g_csr_src[e + 2], sD = g_csr_src[e + 3];
        uint2 hA = h2[(size_t)sA * 32 + lane];
        uint2 hB = h2[(size_t)sB * 32 + lane];
        uint2 hC = h2[(size_t)sC * 32 + lane];
        uint2 hD = h2[(size_t)sD * 32 + lane];
        __half2 pABx = __hadd2(*(__half2*)&hA.x, *(__half2*)&hB.x);
        __half2 pCDx = __hadd2(*(__half2*)&hC.x, *(__half2*)&hD.x);
        __half2 pABy = __hadd2(*(__half2*)&hA.y, *(__half2*)&hB.y);
        __half2 pCDy = __hadd2(*(__half2*)&hC.y, *(__half2*)&hD.y);
        float2 fABx = __half22float2(pABx);
        float2 fCDx = __half22float2(pCDx);
        float2 fABy = __half22float2(pABy);
        float2 fCDy = __half22float2(pCDy);
        ax += fABx.x + fCDx.x;
        ay += fABx.y + fCDx.y;
        az += fABy.x + fCDy.x;
        aw += fABy.y + fCDy.y;
    }
    for (; e < e1; e++) {
        int sA = g_csr_src[e];
        uint2 hA = h2[(size_t)sA * 32 + lane];
        float2 a01 = __half22float2(*(__half2*)&hA.x);
        float2 a23 = __half22float2(*(__half2*)&hA.y);
        ax += a01.x; ay += a01.y; az += a23.x; aw += a23.y;
    }

    float4 bb = *(const float4*)&b1[lane * 4];
    float4 v;
    v.x = fmaxf(fmaf(ax, di, bb.x), 0.f);
    v.y = fmaxf(fmaf(ay, di, bb.y), 0.f);
    v.z = fmaxf(fmaf(az, di, bb.z), 0.f);
    v.w = fmaxf(fmaf(aw, di, bb.w), 0.f);
    *(float4*)&sval[w * CH + lane * 4] = v;
    if (lane == 0) sgid[w] = g_batch[d];
    __syncthreads();

    if (tid < CH) {
        int c = tid;
        int curg = sgid[0];
        float m = sval[c];
        for (int ww = 1; ww < AGG_WARPS; ww++) {
            int g = sgid[ww];
            float u = sval[ww * CH + c];
            if (g == curg) {
                m = fmaxf(m, u);
            } else {
                atomicMax(&g_pooled[curg * CH + c], __float_as_uint(m));
                curg = g; m = u;
            }
        }
        atomicMax(&g_pooled[curg * CH + c], __float_as_uint(m));
    }
}

// ---------------- out = relu(pooled @ W2 + b2); restore invariants ---------
__global__ void k_out(const float* __restrict__ W2, const float* __restrict__ b2,
                      float* __restrict__ out) {
    __shared__ float p[CH];
    int g = blockIdx.x, c = threadIdx.x;
    p[c]      = __uint_as_float(g_pooled[g * CH + c]);
    p[c + 64] = __uint_as_float(g_pooled[g * CH + c + 64]);
    __syncthreads();
    // restore zero-invariants for the next replay
    g_pooled[g * CH + c] = 0u;
    g_pooled[g * CH + c + 64] = 0u;
    {   // block g zeroes cursor slice [g*196, g*196+196) ∩ [0, N_NODES)
        int base = g * 196;
        for (int i = c; i < 196; i += OUTC) {
            int idx = base + i;
            if (idx < N_NODES) g_cursor[idx] = 0;
        }
    }
    float acc = b2[c];
#pragma unroll 8
    for (int k = 0; k < CH; k++)
        acc = fmaf(p[k], W2[k * OUTC + c], acc);
    out[g * OUTC + c] = fmaxf(acc, 0.f);
}

// ---------------- launch ---------------------------------------------------
extern "C" void kernel_launch(void* const* d_in, const int* in_sizes, int n_in,
                              void* d_out, int out_size) {
    const float *x = nullptr, *W1 = nullptr, *b1 = nullptr, *W2 = nullptr, *b2 = nullptr;
    const unsigned *ei = nullptr, *bt = nullptr;
    for (int i = 0; i < n_in; i++) {
        switch (in_sizes[i]) {
            case N_NODES * CH:    x  = (const float*)d_in[i]; break;
            case 2 * N_EDGES:     ei = (const unsigned*)d_in[i]; break;
            case N_NODES:         bt = (const unsigned*)d_in[i]; break;
            case CH * CH:         W1 = (const float*)d_in[i]; break;
            case CH:              b1 = (const float*)d_in[i]; break;
            case CH * OUTC:       W2 = (const float*)d_in[i]; break;
            case OUTC:            b2 = (const float*)d_in[i]; break;
        }
    }
    float* out = (float*)d_out;

    static cudaStream_t sB = nullptr;
    static cudaEvent_t evFork = nullptr, evJoin = nullptr;
    if (!sB) {
        cudaStreamCreateWithFlags(&sB, cudaStreamNonBlocking);
        cudaEventCreateWithFlags(&evFork, cudaEventDisableTiming);
        cudaEventCreateWithFlags(&evJoin, cudaEventDisableTiming);
        cudaFuncSetAttribute(k_gemm, cudaFuncAttributeMaxDynamicSharedMemorySize,
                             GEMM_SMEM);
    }

    // Fork: W-convert+batch (side) + tensor-core GEMM overlap edge prep.
    cudaEventRecord(evFork, 0);
    cudaStreamWaitEvent(sB, evFork, 0);
    k_wconv<<<16, 256, 0, sB>>>(W1, bt);
    k_gemm<<<(N_NODES + GM - 1) / GM, 128, GEMM_SMEM, sB>>>(x);
    cudaEventRecord(evJoin, sB);

    // Main: prep (edges only), join gemm, scale h in place, aggregate, out.
    k_prep<<<(N_EDGES / 2 + 255) / 256, 256>>>(ei);
    cudaStreamWaitEvent(0, evJoin, 0);               // h must exist for k_scale
    k_scale<<<(N_NODES + 63) / 64, 256>>>();
    k_aggregate<<<N_NODES / AGG_WARPS, AGG_WARPS * 32>>>(b1);
    k_out<<<NG, OUTC>>>(W2, b2, out);
}